// round 13
// baseline (speedup 1.0000x reference)
#include <cuda_runtime.h>

#define B_GRAPHS 64
#define D_IN     64
#define D_HID    128
#define D_OUT    128
#define TILE_M   128
#define TPB      256
#define GTPB     1024

// d_out layout (floats)
#define OFF_OUT   0
#define OFF_PD    8192
#define OFF_BV    8384
#define OFF_LF    8448

// ---------------- device scratch ----------------
__device__ int          g_starts[B_GRAPHS + 1];
__device__ float        g_cg[B_GRAPHS * D_HID];
__device__ unsigned int g_umax[B_GRAPHS * D_OUT];

#define NEG_INF __int_as_float(0xff800000)

// ---------------- helpers ----------------
__device__ __forceinline__ unsigned enc_max(float f) {
    unsigned u = __float_as_uint(f);
    return (u & 0x80000000u) ? ~u : (u | 0x80000000u);
}
__device__ __forceinline__ float dec_max(unsigned u) {
    if (u == 0u) return NEG_INF;
    return (u & 0x80000000u) ? __uint_as_float(u & 0x7fffffffu)
                             : __uint_as_float(~u);
}
__device__ __forceinline__ unsigned pack_hl(float x0, float x1, unsigned &lo) {
    unsigned hi;
    asm("cvt.rn.satfinite.bf16x2.f32 %0, %1, %2;" : "=r"(hi) : "f"(x1), "f"(x0));
    float h0 = __uint_as_float(hi << 16);
    float h1 = __uint_as_float(hi & 0xffff0000u);
    float r0 = x0 - h0, r1 = x1 - h1;
    asm("cvt.rn.satfinite.bf16x2.f32 %0, %1, %2;" : "=r"(lo) : "f"(r1), "f"(r0));
    return hi;
}
__device__ __forceinline__ void mma_bf16(float d[4],
    unsigned a0, unsigned a1, unsigned a2, unsigned a3,
    unsigned b0, unsigned b1) {
    asm("mma.sync.aligned.m16n8k16.row.col.f32.bf16.bf16.f32 "
        "{%0,%1,%2,%3}, {%4,%5,%6,%7}, {%8,%9}, {%0,%1,%2,%3};"
        : "+f"(d[0]), "+f"(d[1]), "+f"(d[2]), "+f"(d[3])
        : "r"(a0), "r"(a1), "r"(a2), "r"(a3), "r"(b0), "r"(b1));
}

// ---------------- K0: init ----------------
__global__ void k_init(int N) {
    int i = blockIdx.x * blockDim.x + threadIdx.x;
    if (i < B_GRAPHS * D_OUT) g_umax[i] = 0u;
    if (i < B_GRAPHS)  g_starts[i] = -1;
    if (i == B_GRAPHS) g_starts[B_GRAPHS] = N;
}

// ---------------- K1: segment boundaries ----------------
__global__ void k_bounds(const int* __restrict__ batch, int N) {
    int i = blockIdx.x * blockDim.x + threadIdx.x;
    if (i >= N) return;
    if (i == 0 || batch[i] != batch[i - 1]) g_starts[batch[i]] = i;
}

// ---------------- K2: fill empty segments (smem scan) ----------------
__global__ void k_fill() {
    __shared__ int s[B_GRAPHS + 1];
    int t = threadIdx.x;
    if (t <= B_GRAPHS) s[t] = g_starts[t];
    __syncthreads();
    if (t == 0)
        for (int g = B_GRAPHS - 1; g >= 0; --g)
            if (s[g] < 0) s[g] = s[g + 1];
    __syncthreads();
    if (t < B_GRAPHS) g_starts[t] = s[t];
}

// ---------------- K3: COM, argmin, gathers, c_g (1024 thr) -------------
__global__ void __launch_bounds__(GTPB)
k_graph(const float* __restrict__ x, const float* __restrict__ pos,
        const int* __restrict__ batch, const float* __restrict__ lf,
        const float* __restrict__ W1, const float* __restrict__ b1,
        float* __restrict__ out, int N) {
    __shared__ float swx[32], swy[32], swz[32];
    __shared__ unsigned long long swk[32];
    __shared__ float scom[3], spd[3];
    __shared__ float sxd[D_IN];
    __shared__ int   sidx;

    const int g = blockIdx.x, tid = threadIdx.x;
    const int lane = tid & 31, wid = tid >> 5;
    const int s = g_starts[g], e = g_starts[g + 1];
    const int count = e - s;

    // sum -> COM (warp shuffle reduction; deterministic)
    float fx = 0.f, fy = 0.f, fz = 0.f;
    for (int i = s + tid; i < e; i += GTPB) {
        fx += pos[i*3+0]; fy += pos[i*3+1]; fz += pos[i*3+2];
    }
    #pragma unroll
    for (int d = 16; d > 0; d >>= 1) {
        fx += __shfl_xor_sync(0xffffffffu, fx, d);
        fy += __shfl_xor_sync(0xffffffffu, fy, d);
        fz += __shfl_xor_sync(0xffffffffu, fz, d);
    }
    if (lane == 0) { swx[wid] = fx; swy[wid] = fy; swz[wid] = fz; }
    __syncthreads();
    if (wid == 0) {
        float ax = swx[lane], ay = swy[lane], az = swz[lane];
        #pragma unroll
        for (int d = 16; d > 0; d >>= 1) {
            ax += __shfl_xor_sync(0xffffffffu, ax, d);
            ay += __shfl_xor_sync(0xffffffffu, ay, d);
            az += __shfl_xor_sync(0xffffffffu, az, d);
        }
        if (lane == 0) {
            float c = (float)max(count, 1);
            scom[0] = ax / c; scom[1] = ay / c; scom[2] = az / c;
        }
    }
    __syncthreads();

    // argmin distance (first occurrence)
    const float cx = scom[0], cy = scom[1], cz = scom[2];
    unsigned long long best = ~0ULL;
    for (int i = s + tid; i < e; i += GTPB) {
        float dx = pos[i*3+0]-cx, dy = pos[i*3+1]-cy, dz = pos[i*3+2]-cz;
        float d = sqrtf(dx*dx + dy*dy + dz*dz);
        unsigned long long key = ((unsigned long long)__float_as_uint(d) << 32) | (unsigned)i;
        best = min(best, key);
    }
    #pragma unroll
    for (int d = 16; d > 0; d >>= 1)
        best = min(best, __shfl_xor_sync(0xffffffffu, best, d));
    if (lane == 0) swk[wid] = best;
    __syncthreads();
    if (wid == 0) {
        unsigned long long b = swk[lane];
        #pragma unroll
        for (int d = 16; d > 0; d >>= 1)
            b = min(b, __shfl_xor_sync(0xffffffffu, b, d));
        if (lane == 0) sidx = (count == 0) ? (N - 1) : (int)(b & 0xffffffffu);
    }
    __syncthreads();
    const int idx = sidx;

    if (tid < D_IN) sxd[tid] = x[idx * D_IN + tid];
    if (tid < 3) { spd[tid] = pos[idx*3+tid]; out[OFF_PD + g*3 + tid] = spd[tid]; }
    if (tid == 0) out[OFF_BV + g] = (float)batch[idx];
    if (tid < 9)  out[OFF_LF + g*9 + tid] = lf[idx*9 + tid];
    __syncthreads();

    // c_g: 1024 threads = 128 cols x 8 k-lanes
    {
        int j = tid >> 3, kl = tid & 7;
        float acc = (kl == 0) ? b1[j] : 0.f;
        #pragma unroll
        for (int k = kl; k < D_IN; k += 8)
            acc += sxd[k] * (W1[k*D_HID + j] - W1[(D_IN+k)*D_HID + j]);
        if (kl < 3) acc -= spd[kl] * W1[(2*D_IN+kl)*D_HID + j];
        acc += __shfl_xor_sync(0xffffffffu, acc, 1);
        acc += __shfl_xor_sync(0xffffffffu, acc, 2);
        acc += __shfl_xor_sync(0xffffffffu, acc, 4);
        if (kl == 0) g_cg[g*D_HID + j] = acc;
    }
}

// ---------------- shared layout for k_main (32-bit word offsets) --------
// W1frag: [n=128][ks=5][qc=4] uint4                     = 10240 words
// W2frag: [n=128][ks-slot=9][qc=4] uint4 (8 used)       = 18432 words
// Afrag double buffer: 2 x (H 5120 + L 5120)            = 20480 words
#define OW1    0
#define OW2    10240
#define OA0H   28672
#define OA0L   33792
#define OA1H   38912
#define OA1L   44032
#define OB2    49152
#define OCG0   49280
#define OCG1   49536
#define OSB0   49792
#define OSB1   49924
#define SMEM_U32 50056
#define SMEM_BYTES (SMEM_U32 * 4)

// ---------------- K4: fused MLP + segment-max, tensor-core v4 -----------
__global__ void __launch_bounds__(TPB, 1)
k_main(const float* __restrict__ x, const float* __restrict__ pos,
       const int* __restrict__ batch,
       const float* __restrict__ W1, const float* __restrict__ W2,
       const float* __restrict__ b2, int N, int nTiles) {
    extern __shared__ unsigned sm[];
    uint4* sm4 = (uint4*)sm;
    float* smf = (float*)sm;
    int*   smi = (int*)sm;

    const int tid  = threadIdx.x;
    const int lane = tid & 31;
    const int warp = tid >> 5;
    const int qc   = lane & 3;
    const int ns   = lane >> 2;
    const int r0   = (warp << 4) + ns;   // rows r0, r0+8 within tile

    // ---- one-time: W1 fragments ----
    for (int q = tid; q < 128 * 5 * 4; q += TPB) {
        int n = q / 20, rem = q % 20, ks = rem >> 2, qw = rem & 3;
        int kw0 = ks * 8 + qw, kw1 = kw0 + 4;
        float f[4];
        #pragma unroll
        for (int t = 0; t < 4; ++t) {
            int k = (t < 2) ? (2 * kw0 + t) : (2 * kw1 + (t - 2));
            f[t] = (k < 64) ? W1[(64 + k) * D_HID + n]
                 : (k < 67) ? W1[(128 + (k - 64)) * D_HID + n] : 0.f;
        }
        unsigned l0, h0 = pack_hl(f[0], f[1], l0);
        unsigned l1, h1 = pack_hl(f[2], f[3], l1);
        sm4[OW1 / 4 + q] = make_uint4(h0, h1, l0, l1);
    }
    // ---- one-time: W2 fragments ----
    for (int q = tid; q < 128 * 8 * 4; q += TPB) {
        int n = q >> 5, rem = q & 31, ks = rem >> 2, qw = rem & 3;
        int kw0 = ks * 8 + qw, kw1 = kw0 + 4;
        float f00 = W2[(2 * kw0)     * D_OUT + n];
        float f01 = W2[(2 * kw0 + 1) * D_OUT + n];
        float f10 = W2[(2 * kw1)     * D_OUT + n];
        float f11 = W2[(2 * kw1 + 1) * D_OUT + n];
        unsigned l0, h0 = pack_hl(f00, f01, l0);
        unsigned l1, h1 = pack_hl(f10, f11, l1);
        sm4[OW2 / 4 + (n * 9 + ks) * 4 + qw] = make_uint4(h0, h1, l0, l1);
    }
    if (tid < D_OUT) smf[OB2 + tid] = b2[tid];
    // ---- one-time: zero ks=4 A pad region in BOTH buffers ----
    {
        int wb = tid >> 5, ln = tid & 31;
        sm4[OA0H / 4 + (wb * 5 + 4) * 32 + ln] = make_uint4(0, 0, 0, 0);
        sm4[OA0L / 4 + (wb * 5 + 4) * 32 + ln] = make_uint4(0, 0, 0, 0);
        sm4[OA1H / 4 + (wb * 5 + 4) * 32 + ln] = make_uint4(0, 0, 0, 0);
        sm4[OA1L / 4 + (wb * 5 + 4) * 32 + ln] = make_uint4(0, 0, 0, 0);
    }

    const float4* X4 = (const float4*)x;
    const int tpc = (nTiles + gridDim.x - 1) / gridDim.x;
    const int t0  = blockIdx.x * tpc;
    const int t1  = min(t0 + tpc, nTiles);

    float4 xv[8];
    float  pp0 = 0.f, pp1 = 0.f, pp2 = 0.f, cgv = 0.f;
    int    pb = -1, pgF = 0;

#define PREFETCH(T) do {                                                      \
    int node0_ = (T) * TILE_M;                                                \
    _Pragma("unroll")                                                         \
    for (int i_ = 0; i_ < 8; ++i_) {                                          \
        int q_ = tid + i_ * TPB; int nd_ = q_ >> 4, kq_ = q_ & 15;            \
        int gn_ = node0_ + nd_;                                               \
        xv[i_] = (gn_ < N) ? X4[gn_ * 16 + kq_]                               \
                           : make_float4(0.f, 0.f, 0.f, 0.f);                 \
    }                                                                         \
    pgF = batch[node0_];                                                      \
    if (tid < TILE_M) {                                                       \
        int gn_ = node0_ + tid;                                               \
        if (gn_ < N) { pp0 = pos[gn_*3]; pp1 = pos[gn_*3+1];                  \
                       pp2 = pos[gn_*3+2]; pb = batch[gn_]; }                 \
        else { pp0 = pp1 = pp2 = 0.f; pb = -1; }                              \
    }                                                                         \
    if (tid < 128) cgv = g_cg[pgF * D_HID + tid];                             \
    else           cgv = g_cg[min(pgF + 1, B_GRAPHS - 1) * D_HID + (tid - 128)]; \
} while (0)

// scatter the most recent PREFETCH into buffer q (0/1)
#define STORE_TILE(Q) do {                                                    \
    const int oah_ = (Q) ? OA1H : OA0H;                                       \
    const int oal_ = (Q) ? OA1L : OA0L;                                       \
    const int osb_ = (Q) ? OSB1 : OSB0;                                       \
    const int ocg_ = (Q) ? OCG1 : OCG0;                                       \
    _Pragma("unroll")                                                         \
    for (int i_ = 0; i_ < 8; ++i_) {                                          \
        int q_ = tid + i_ * TPB; int nd_ = q_ >> 4, kq_ = q_ & 15;            \
        int wb_ = nd_ >> 4, lr_ = nd_ & 7, rb_ = (nd_ >> 3) & 1;              \
        int kw0_ = 2 * kq_;                                                   \
        int ks_ = kw0_ >> 3, w0_ = kw0_ & 7;                                  \
        int slot_ = (w0_ >> 2) * 2 + rb_;                                     \
        int idx4_ = (wb_ * 5 + ks_) * 32 + lr_ * 4 + (w0_ & 3);               \
        unsigned lo0_, hi0_ = pack_hl(xv[i_].x, xv[i_].y, lo0_);              \
        sm[oah_ + idx4_ * 4 + slot_] = hi0_;                                  \
        sm[oal_ + idx4_ * 4 + slot_] = lo0_;                                  \
        unsigned lo1_, hi1_ = pack_hl(xv[i_].z, xv[i_].w, lo1_);              \
        sm[oah_ + (idx4_ + 1) * 4 + slot_] = hi1_;                            \
        sm[oal_ + (idx4_ + 1) * 4 + slot_] = lo1_;                            \
    }                                                                         \
    if (tid < TILE_M) {                                                       \
        int nd_ = tid, wb_ = nd_ >> 4, lr_ = nd_ & 7, rb_ = (nd_ >> 3) & 1;   \
        int base4_ = (wb_ * 5 + 4) * 32 + lr_ * 4;                            \
        unsigned lo0_, hi0_ = pack_hl(pp0, pp1, lo0_);                        \
        sm[oah_ + (base4_ + 0) * 4 + rb_] = hi0_;                             \
        sm[oal_ + (base4_ + 0) * 4 + rb_] = lo0_;                             \
        unsigned lo1_, hi1_ = pack_hl(pp2, 0.f, lo1_);                        \
        sm[oah_ + (base4_ + 1) * 4 + rb_] = hi1_;                             \
        sm[oal_ + (base4_ + 1) * 4 + rb_] = lo1_;                             \
        smi[osb_ + nd_] = pb;                                                 \
    }                                                                         \
    if (tid == 0) smi[osb_ + 128] = pgF;                                      \
    smf[ocg_ + tid] = cgv;                                                    \
} while (0)

    int accG = -1;
    float runm0[16], runm1[16];
    #pragma unroll
    for (int j = 0; j < 16; ++j) { runm0[j] = NEG_INF; runm1[j] = NEG_INF; }

#define FLUSH_RUNMAX() do {                                                   \
    _Pragma("unroll")                                                         \
    for (int j_ = 0; j_ < 16; ++j_) {                                         \
        runm0[j_] = fmaxf(runm0[j_], __shfl_xor_sync(0xffffffffu, runm0[j_], 4));  \
        runm0[j_] = fmaxf(runm0[j_], __shfl_xor_sync(0xffffffffu, runm0[j_], 8));  \
        runm0[j_] = fmaxf(runm0[j_], __shfl_xor_sync(0xffffffffu, runm0[j_], 16)); \
        runm1[j_] = fmaxf(runm1[j_], __shfl_xor_sync(0xffffffffu, runm1[j_], 4));  \
        runm1[j_] = fmaxf(runm1[j_], __shfl_xor_sync(0xffffffffu, runm1[j_], 8));  \
        runm1[j_] = fmaxf(runm1[j_], __shfl_xor_sync(0xffffffffu, runm1[j_], 16)); \
    }                                                                         \
    if (lane < 4) {                                                           \
        _Pragma("unroll")                                                     \
        for (int j_ = 0; j_ < 16; ++j_) {                                     \
            int col_ = j_ * 8 + 2 * qc;                                       \
            atomicMax(&g_umax[accG * D_OUT + col_],                           \
                      enc_max(runm0[j_] + smf[OB2 + col_]));                  \
            atomicMax(&g_umax[accG * D_OUT + col_ + 1],                       \
                      enc_max(runm1[j_] + smf[OB2 + col_ + 1]));              \
        }                                                                     \
    }                                                                         \
    _Pragma("unroll")                                                         \
    for (int j_ = 0; j_ < 16; ++j_) { runm0[j_] = NEG_INF; runm1[j_] = NEG_INF; } \
} while (0)

    // preamble: fill buffer for first tile, start LDG for second
    if (t0 < t1) { PREFETCH(t0); STORE_TILE(t0 & 1); }
    if (t0 + 1 < t1) PREFETCH(t0 + 1);

    for (int tile = t0; tile < t1; ++tile) {
        const int p = tile & 1;
        const int oah = p ? OA1H : OA0H;
        const int oal = p ? OA1L : OA0L;
        const int osb = p ? OSB1 : OSB0;
        const int ocg = p ? OCG1 : OCG0;

        __syncthreads();   // publish STS(tile); prior reads of other buffer done

        const int gF = smi[osb + 128];
        if (gF != accG) {
            if (accG >= 0) FLUSH_RUNMAX();
            accG = gF;
        }

        // ---- stage 1: y = x@W1b + pos@W1c (3-pass split bf16) ----
        float acc[16][4];
        #pragma unroll
        for (int j = 0; j < 16; ++j)
            acc[j][0] = acc[j][1] = acc[j][2] = acc[j][3] = 0.f;
        #pragma unroll
        for (int ks = 0; ks < 5; ++ks) {
            uint4 aH = sm4[oah / 4 + (warp * 5 + ks) * 32 + lane];
            uint4 aL = sm4[oal / 4 + (warp * 5 + ks) * 32 + lane];
            #pragma unroll
            for (int j = 0; j < 16; ++j) {
                uint4 b = sm4[OW1 / 4 + ((j * 8 + ns) * 5 + ks) * 4 + qc];
                mma_bf16(acc[j], aH.x, aH.y, aH.z, aH.w, b.x, b.y);
                mma_bf16(acc[j], aL.x, aL.y, aL.z, aL.w, b.x, b.y);
                mma_bf16(acc[j], aH.x, aH.y, aH.z, aH.w, b.z, b.w);
            }
        }

        // ---- overlap: scatter next tile, start LDG for tile+2 ----
        if (tile + 1 < t1) STORE_TILE((tile + 1) & 1);
        if (tile + 2 < t1) PREFETCH(tile + 2);

        // ---- epilogue 1: +c_g, relu, repack to stage-2 A frags ----
        const int gA  = smi[osb + r0];
        const int gB  = smi[osb + r0 + 8];
        const int gLo = smi[osb + (warp << 4)];
        const int gHi = smi[osb + (warp << 4) + 15];
        const float* cgA = (gA == gF)     ? (smf + ocg)
                         : (gA == gF + 1) ? (smf + ocg + 128)
                         : (gA >= 0)      ? (g_cg + gA * D_HID)
                                          : (smf + ocg);
        const float* cgB = (gB == gF)     ? (smf + ocg)
                         : (gB == gF + 1) ? (smf + ocg + 128)
                         : (gB >= 0)      ? (g_cg + gB * D_HID)
                                          : (smf + ocg);
        unsigned ah[8][4], al[8][4];
        #pragma unroll
        for (int j = 0; j < 16; ++j) {
            int col = j * 8 + 2 * qc;
            float v0 = fmaxf(acc[j][0] + cgA[col],     0.f);
            float v1 = fmaxf(acc[j][1] + cgA[col + 1], 0.f);
            float v2 = fmaxf(acc[j][2] + cgB[col],     0.f);
            float v3 = fmaxf(acc[j][3] + cgB[col + 1], 0.f);
            unsigned l01, h01 = pack_hl(v0, v1, l01);
            unsigned l23, h23 = pack_hl(v2, v3, l23);
            int k2 = j >> 1, off = (j & 1) * 2;
            ah[k2][off]     = h01;  al[k2][off]     = l01;
            ah[k2][off + 1] = h23;  al[k2][off + 1] = l23;
        }

        // ---- stage 2: msg = h@W2 (A in registers) ----
        float a2c[16][4];
        #pragma unroll
        for (int j = 0; j < 16; ++j)
            a2c[j][0] = a2c[j][1] = a2c[j][2] = a2c[j][3] = 0.f;
        #pragma unroll
        for (int ks = 0; ks < 8; ++ks) {
            #pragma unroll
            for (int j = 0; j < 16; ++j) {
                uint4 b = sm4[OW2 / 4 + ((j * 8 + ns) * 9 + ks) * 4 + qc];
                mma_bf16(a2c[j], ah[ks][0], ah[ks][1], ah[ks][2], ah[ks][3], b.x, b.y);
                mma_bf16(a2c[j], al[ks][0], al[ks][1], al[ks][2], al[ks][3], b.x, b.y);
                mma_bf16(a2c[j], ah[ks][0], ah[ks][1], ah[ks][2], ah[ks][3], b.z, b.w);
            }
        }

        // ---- stage 3: segment max ----
        if (gLo == gHi && gLo == accG) {
            // fast: accumulate into cross-tile register run-max (b2 at flush)
            #pragma unroll
            for (int j = 0; j < 16; ++j) {
                runm0[j] = fmaxf(runm0[j], fmaxf(a2c[j][0], a2c[j][2]));
                runm1[j] = fmaxf(runm1[j], fmaxf(a2c[j][1], a2c[j][3]));
            }
        } else {
            // slow: boundary / mixed / pad rows -> direct global atomics
            #pragma unroll
            for (int j = 0; j < 16; ++j) {
                int col = j * 8 + 2 * qc;
                float b0v = smf[OB2 + col], b1v = smf[OB2 + col + 1];
                if (gA >= 0) {
                    atomicMax(&g_umax[gA * D_OUT + col],     enc_max(a2c[j][0] + b0v));
                    atomicMax(&g_umax[gA * D_OUT + col + 1], enc_max(a2c[j][1] + b1v));
                }
                if (gB >= 0) {
                    atomicMax(&g_umax[gB * D_OUT + col],     enc_max(a2c[j][2] + b0v));
                    atomicMax(&g_umax[gB * D_OUT + col + 1], enc_max(a2c[j][3] + b1v));
                }
            }
        }
    }

    if (accG >= 0) FLUSH_RUNMAX();
#undef PREFETCH
#undef STORE_TILE
#undef FLUSH_RUNMAX
}

// ---------------- K5: decode maxima ----------------
__global__ void k_out(float* __restrict__ out) {
    int i = blockIdx.x * blockDim.x + threadIdx.x;
    if (i < B_GRAPHS * D_OUT) out[OFF_OUT + i] = dec_max(g_umax[i]);
}

// ---------------- entry ----------------
extern "C" void kernel_launch(void* const* d_in, const int* in_sizes, int n_in,
                              void* d_out, int out_size) {
    const float* x     = (const float*)d_in[0];
    const float* pos   = (const float*)d_in[1];
    const int*   batch = (const int*)  d_in[2];
    const float* lf    = (const float*)d_in[3];
    const float* W1    = (const float*)d_in[4];
    const float* b1    = (const float*)d_in[5];
    const float* W2    = (const float*)d_in[6];
    const float* b2    = (const float*)d_in[7];
    float* out = (float*)d_out;

    const int N = in_sizes[2];
    const int nTiles = (N + TILE_M - 1) / TILE_M;

    int nsm = 148;
    cudaDeviceGetAttribute(&nsm, cudaDevAttrMultiProcessorCount, 0);
    if (nsm <= 0) nsm = 148;

    cudaFuncSetAttribute(k_main, cudaFuncAttributeMaxDynamicSharedMemorySize,
                         SMEM_BYTES);

    k_init  <<<(B_GRAPHS * D_OUT + TPB - 1) / TPB, TPB>>>(N);
    k_bounds<<<(N + TPB - 1) / TPB, TPB>>>(batch, N);
    k_fill  <<<1, 128>>>();
    k_graph <<<B_GRAPHS, GTPB>>>(x, pos, batch, lf, W1, b1, out, N);
    k_main  <<<nsm, TPB, SMEM_BYTES>>>(x, pos, batch, W1, W2, b2, N, nTiles);
    k_out   <<<(B_GRAPHS * D_OUT + TPB - 1) / TPB, TPB>>>(out);
}